// round 8
// baseline (speedup 1.0000x reference)
#include <cuda_runtime.h>
#include <cuda_fp16.h>
#include <cuda_bf16.h>
#include <cstdint>

// TokenAwareEmbedding: per-token NF4 dequant + special-token override.
//   0: input_ids          int32|int64 [8, 2048]
//   1: main_quantized     int32       [804112, 64]
//   2: main_scales        fp32        [804112]
//   3: special_embeddings fp32|fp16|bf16 [256, 1024]
//   4: special_indices    int32|int64 [256] (sorted)
// output: fp32 [8, 2048, 1024]

#define VOCAB 50257
#define DIM 1024
#define NTOK (8 * 2048)
#define NSPEC 256
#define TPB 8                   // tokens per block
#define ROW_BYTES 4096          // one token row: 1024 x 4B

__constant__ float c_nf4[16] = {
    -1.0f, -0.6962f, -0.5251f, -0.3949f, -0.2844f, -0.1848f, -0.0911f, 0.0f,
    0.0796f, 0.1609f, 0.2461f, 0.3379f, 0.4407f, 0.5626f, 0.723f, 1.0f};

// packed per-token record: t[0:16) | (row+1)[16:25) | dt[25:27)
__device__ int g_rec[NTOK];

__device__ __forceinline__ float finite_abs(float v) {
    return isfinite(v) ? fabsf(v) : 1e30f;
}

__device__ __forceinline__ uint32_t smem_u32(const void* p) {
    uint32_t a;
    asm("{ .reg .u64 t; cvta.to.shared.u64 t, %1; cvt.u32.u64 %0, t; }"
        : "=r"(a) : "l"(p));
    return a;
}

// ── K1: per-token record; detection fused (each block re-detects, L2-cheap) ─
__global__ __launch_bounds__(256)
void prep_rec_kernel(const void* __restrict__ ids,
                     const void* __restrict__ sidx,
                     const unsigned short* __restrict__ specu) {
    __shared__ int   s_sidx[NSPEC];
    __shared__ float s_sum[3][8];
    __shared__ float s_max[3][8];
    __shared__ int   s_info;  // wide | dt<<1
    const int tid = threadIdx.x;

    float sum[3] = {0.f, 0.f, 0.f};
    float mx[3] = {0.f, 0.f, 0.f};
    #pragma unroll
    for (int k = 0; k < 4; k++) {
        int i = tid * 4 + k;
        float vh = finite_abs(__half2float(((const __half*)specu)[i]));
        float vb = finite_abs(__bfloat162float(((const __nv_bfloat16*)specu)[i]));
        float vf = finite_abs(((const float*)specu)[i]);
        sum[0] += vh; mx[0] = fmaxf(mx[0], vh);
        sum[1] += vb; mx[1] = fmaxf(mx[1], vb);
        sum[2] += vf; mx[2] = fmaxf(mx[2], vf);
    }
    #pragma unroll
    for (int c = 0; c < 3; c++) {
        #pragma unroll
        for (int o = 16; o > 0; o >>= 1) {
            sum[c] += __shfl_down_sync(0xFFFFFFFFu, sum[c], o);
            mx[c] = fmaxf(mx[c], __shfl_down_sync(0xFFFFFFFFu, mx[c], o));
        }
        if ((tid & 31) == 0) { s_sum[c][tid >> 5] = sum[c]; s_max[c][tid >> 5] = mx[c]; }
    }
    __syncthreads();
    if (tid == 0) {
        float S[3], M[3];
        #pragma unroll
        for (int c = 0; c < 3; c++) {
            S[c] = 0.f; M[c] = 0.f;
            #pragma unroll
            for (int w = 0; w < 8; w++) { S[c] += s_sum[c][w]; M[c] = fmaxf(M[c], s_max[c][w]); }
            S[c] *= (1.0f / 1024.0f);  // mean |x|; N(0,1) -> ~0.798
        }
        int dt;
        if (M[0] < 10.f && fabsf(S[0] - 0.8f) < 0.3f)      dt = 1;  // fp16
        else if (M[1] < 10.f && fabsf(S[1] - 0.8f) < 0.3f) dt = 2;  // bf16
        else                                                dt = 0;  // fp32

        const int* w32 = (const int*)ids;
        bool wide = true;
        #pragma unroll
        for (int k = 1; k < 64; k += 2) wide &= (w32[k] == 0);
        s_info = (wide ? 1 : 0) | (dt << 1);
    }
    __syncthreads();
    const bool wide = (s_info & 1) != 0;
    const int  dt   = s_info >> 1;

    s_sidx[tid] = wide ? (int)((const long long*)sidx)[tid]
                       : ((const int*)sidx)[tid];
    __syncthreads();

    const int tok = blockIdx.x * 256 + tid;
    long long tl = wide ? ((const long long*)ids)[tok]
                        : (long long)((const int*)ids)[tok];
    if (tl < 0) tl = 0;
    if (tl >= VOCAB) tl = VOCAB - 1;
    const int t = (int)tl;

    int lo = 0, hi = NSPEC;
    #pragma unroll
    for (int it = 0; it < 8; it++) {
        int mid = (lo + hi) >> 1;
        if (s_sidx[mid] <= t) lo = mid + 1; else hi = mid;
    }
    const int r = (lo > 0 && s_sidx[lo - 1] == t) ? (lo - 1) : -1;
    g_rec[tok] = t | ((r + 1) << 16) | (dt << 25);
}

// ── K2: bulk-async pipeline: TMA-load 8 rows -> dequant in SMEM -> TMA-store ─
__global__ __launch_bounds__(256)
void tok_embed_kernel(const int* __restrict__ quant,
                      const float* __restrict__ scales,
                      const unsigned short* __restrict__ specu,
                      float* __restrict__ out) {
    __shared__ __align__(128) unsigned char buf[TPB * ROW_BYTES];  // 32 KB
    __shared__ __align__(8) unsigned long long mbar;

    const int tid = threadIdx.x;
    const int tok0 = blockIdx.x * TPB;
    const int4 ra = *reinterpret_cast<const int4*>(g_rec + tok0);  // broadcast
    const int4 rb = *reinterpret_cast<const int4*>(g_rec + tok0 + 4);
    const int rec[TPB] = {ra.x, ra.y, ra.z, ra.w, rb.x, rb.y, rb.z, rb.w};

    const uint32_t sbuf = smem_u32(buf);
    const uint32_t mb = smem_u32(&mbar);

    if (tid == 0) {
        asm volatile("mbarrier.init.shared.b64 [%0], %1;" :: "r"(mb), "r"(1) : "memory");
    }
    __syncthreads();

    // Issue 8 bulk async loads (4 KB each) from one thread.
    if (tid == 0) {
        asm volatile("mbarrier.arrive.expect_tx.shared.b64 _, [%0], %1;"
                     :: "r"(mb), "r"((uint32_t)(TPB * ROW_BYTES)) : "memory");
        #pragma unroll
        for (int j = 0; j < TPB; j++) {
            const int t = rec[j] & 0xFFFF;
            const void* src = quant + (size_t)t * DIM;
            asm volatile(
                "cp.async.bulk.shared::cluster.global.mbarrier::complete_tx::bytes "
                "[%0], [%1], %2, [%3];"
                :: "r"(sbuf + j * ROW_BYTES), "l"(src),
                   "r"((uint32_t)ROW_BYTES), "r"(mb) : "memory");
        }
    }

    // Overlap: scale loads (L2 broadcast) while bulk loads fly.
    const int d = tid * 4;
    float sc[TPB];
    #pragma unroll
    for (int j = 0; j < TPB; j++)
        sc[j] = __ldg(scales + (rec[j] & 0xFFFF) * (DIM / 64) + (d >> 6));

    // Wait for all 32 KB to land (acquire).
    {
        uint32_t done;
        asm volatile(
            "{\n\t.reg .pred p;\n\t"
            "mbarrier.try_wait.parity.acquire.cta.shared::cta.b64 p, [%1], %2;\n\t"
            "selp.b32 %0, 1, 0, p;\n\t}"
            : "=r"(done) : "r"(mb), "r"(0u) : "memory");
        while (!done) {
            asm volatile(
                "{\n\t.reg .pred p;\n\t"
                "mbarrier.try_wait.parity.acquire.cta.shared::cta.b64 p, [%1], %2, 0x989680;\n\t"
                "selp.b32 %0, 1, 0, p;\n\t}"
                : "=r"(done) : "r"(mb), "r"(0u) : "memory");
        }
    }

    // Dequant in place: each thread owns 16 B per row.
    #pragma unroll
    for (int j = 0; j < TPB; j++) {
        const int r = ((rec[j] >> 16) & 0x1FF) - 1;
        float4 o;
        if (r >= 0) {
            const int dt = (rec[j] >> 25) & 3;
            const size_t base = (size_t)r * DIM + d;
            if (dt == 0) {
                o = *reinterpret_cast<const float4*>((const float*)specu + base);
            } else if (dt == 1) {
                const __half2* sp = reinterpret_cast<const __half2*>((const __half*)specu + base);
                float2 fa = __half22float2(sp[0]);
                float2 fb = __half22float2(sp[1]);
                o = make_float4(fa.x, fa.y, fb.x, fb.y);
            } else {
                const __nv_bfloat162* sp =
                    reinterpret_cast<const __nv_bfloat162*>((const __nv_bfloat16*)specu + base);
                float2 fa = __bfloat1622float2(sp[0]);
                float2 fb = __bfloat1622float2(sp[1]);
                o = make_float4(fa.x, fa.y, fb.x, fb.y);
            }
        } else {
            const int4 q = *reinterpret_cast<const int4*>(buf + j * ROW_BYTES + d * 4);
            const float s = sc[j];
            o = make_float4(c_nf4[q.x & 15] * s, c_nf4[q.y & 15] * s,
                            c_nf4[q.z & 15] * s, c_nf4[q.w & 15] * s);
        }
        *reinterpret_cast<float4*>(buf + j * ROW_BYTES + d * 4) = o;
    }
    __syncthreads();
    asm volatile("fence.proxy.async.shared::cta;" ::: "memory");

    // Bulk async stores: 8 x 4 KB SMEM -> GMEM.
    if (tid == 0) {
        #pragma unroll
        for (int j = 0; j < TPB; j++) {
            void* dst = out + (size_t)(tok0 + j) * DIM;
            asm volatile(
                "cp.async.bulk.global.shared::cta.bulk_group [%0], [%1], %2;"
                :: "l"(dst), "r"(sbuf + j * ROW_BYTES),
                   "r"((uint32_t)ROW_BYTES) : "memory");
        }
        asm volatile("cp.async.bulk.commit_group;" ::: "memory");
        asm volatile("cp.async.bulk.wait_group 0;" ::: "memory");
    }
}

extern "C" void kernel_launch(void* const* d_in, const int* in_sizes, int n_in,
                              void* d_out, int out_size) {
    const void*  ids    = d_in[0];
    const int*   quant  = (const int*)d_in[1];
    const float* scales = (const float*)d_in[2];
    const unsigned short* spec = (const unsigned short*)d_in[3];
    const void*  sidx   = d_in[4];
    float* out = (float*)d_out;

    prep_rec_kernel<<<NTOK / 256, 256>>>(ids, sidx, spec);
    tok_embed_kernel<<<NTOK / TPB, 256>>>(quant, scales, spec, out);
}

// round 10
// speedup vs baseline: 1.0609x; 1.0609x over previous
#include <cuda_runtime.h>
#include <cuda_fp16.h>
#include <cuda_bf16.h>
#include <cstdint>

// TokenAwareEmbedding: per-token NF4 dequant + special-token override.
// Single fused kernel: per-CTA dtype/width detection (L2-hot, ~1KB) +
// special-index binary search + batched gather/dequant.
//   0: input_ids          int32|int64 [8, 2048]
//   1: main_quantized     int32       [804112, 64]
//   2: main_scales        fp32        [804112]
//   3: special_embeddings fp32|fp16|bf16 [256, 1024]
//   4: special_indices    int32|int64 [256] (sorted)
// output: fp32 [8, 2048, 1024]

#define VOCAB 50257
#define DIM 1024
#define NTOK (8 * 2048)
#define NSPEC 256
#define TPB 8            // tokens per block

__constant__ float c_nf4[16] = {
    -1.0f, -0.6962f, -0.5251f, -0.3949f, -0.2844f, -0.1848f, -0.0911f, 0.0f,
    0.0796f, 0.1609f, 0.2461f, 0.3379f, 0.4407f, 0.5626f, 0.723f, 1.0f};

__device__ __forceinline__ float finite_abs(float v) {
    return isfinite(v) ? fabsf(v) : 1e30f;
}

__global__ __launch_bounds__(256)
void tok_embed_kernel(const void* __restrict__ ids,
                      const int* __restrict__ quant,
                      const float* __restrict__ scales,
                      const unsigned short* __restrict__ specu,
                      const void* __restrict__ sidx,
                      float* __restrict__ out) {
    __shared__ int   s_sidx[NSPEC];
    __shared__ int   s_rec[TPB];
    __shared__ float s_sum[2][8];
    __shared__ float s_max[2][8];
    __shared__ int   s_dt;
    const int tid = threadIdx.x;
    const int tok0 = blockIdx.x * TPB;

    // ── width detection: int64 ids have zero odd int32 words (L2 broadcast) ──
    const int* w32 = (const int*)ids;
    const int accw = w32[1] | w32[3] | w32[5] | w32[7] |
                     w32[9] | w32[11] | w32[13] | w32[15];
    const bool wide = (accw == 0);   // uniform across all threads

    // ── special indices -> shared ──
    s_sidx[tid] = wide ? (int)((const long long*)sidx)[tid]
                       : ((const int*)sidx)[tid];

    // ── dtype detection: 1 sample/thread from first 256 spec values ──
    // mean |x| of N(0,1) ~ 0.798. bf16-read-as-fp16 -> mean ~1.8 (reject);
    // fp32-read-as-fp16/bf16 -> NaN/huge max (reject).
    float vh = finite_abs(__half2float(((const __half*)specu)[tid]));
    float vb = finite_abs(__bfloat162float(((const __nv_bfloat16*)specu)[tid]));
    float sum[2] = {vh, vb};
    float mx[2]  = {vh, vb};
    #pragma unroll
    for (int c = 0; c < 2; c++) {
        #pragma unroll
        for (int o = 16; o > 0; o >>= 1) {
            sum[c] += __shfl_down_sync(0xFFFFFFFFu, sum[c], o);
            mx[c] = fmaxf(mx[c], __shfl_down_sync(0xFFFFFFFFu, mx[c], o));
        }
        if ((tid & 31) == 0) { s_sum[c][tid >> 5] = sum[c]; s_max[c][tid >> 5] = mx[c]; }
    }
    __syncthreads();
    if (tid == 0) {
        float S[2], M[2];
        #pragma unroll
        for (int c = 0; c < 2; c++) {
            S[c] = 0.f; M[c] = 0.f;
            #pragma unroll
            for (int w = 0; w < 8; w++) { S[c] += s_sum[c][w]; M[c] = fmaxf(M[c], s_max[c][w]); }
            S[c] *= (1.0f / 256.0f);
        }
        int dt;
        if (M[0] < 10.f && fabsf(S[0] - 0.8f) < 0.3f)      dt = 1;  // fp16
        else if (M[1] < 10.f && fabsf(S[1] - 0.8f) < 0.3f) dt = 2;  // bf16
        else                                                dt = 0;  // fp32
        s_dt = dt;
    }
    // ── per-CTA records: threads 0..7 each resolve one token ──
    if (tid < TPB) {
        const int tok = tok0 + tid;
        long long tl = wide ? ((const long long*)ids)[tok]
                            : (long long)((const int*)ids)[tok];
        if (tl < 0) tl = 0;
        if (tl >= VOCAB) tl = VOCAB - 1;
        const int t = (int)tl;
        // upper_bound; last-wins for duplicate sorted indices (XLA scatter)
        int lo = 0, hi = NSPEC;
        #pragma unroll
        for (int it = 0; it < 8; it++) {
            int mid = (lo + hi) >> 1;
            if (s_sidx[mid] <= t) lo = mid + 1; else hi = mid;
        }
        const int r = (lo > 0 && s_sidx[lo - 1] == t) ? (lo - 1) : -1;
        s_rec[tid] = t | ((r + 1) << 16);
    }
    __syncthreads();

    const int dt = s_dt;
    int rec[TPB];
    #pragma unroll
    for (int j = 0; j < TPB; j++) rec[j] = s_rec[j];

    const int d = tid * 4;  // 4 consecutive dims per thread

    // ── Phase 1: front-batch all independent loads (no control flow) ──
    int4 q[TPB];
    float sc[TPB];
    #pragma unroll
    for (int j = 0; j < TPB; j++) {
        const int t = rec[j] & 0xFFFF;
        q[j] = *reinterpret_cast<const int4*>(quant + (size_t)t * DIM + d);
        sc[j] = __ldg(scales + t * (DIM / 64) + (d >> 6));
    }

    // ── Phase 2: compute + streaming stores (rare special branch only here) ──
    #pragma unroll
    for (int j = 0; j < TPB; j++) {
        const int r = ((rec[j] >> 16) & 0x1FF) - 1;
        float4 o;
        if (r >= 0) {
            const size_t base = (size_t)r * DIM + d;
            if (dt == 0) {
                o = *reinterpret_cast<const float4*>((const float*)specu + base);
            } else if (dt == 1) {
                const __half2* sp = reinterpret_cast<const __half2*>((const __half*)specu + base);
                float2 fa = __half22float2(sp[0]);
                float2 fb = __half22float2(sp[1]);
                o = make_float4(fa.x, fa.y, fb.x, fb.y);
            } else {
                const __nv_bfloat162* sp =
                    reinterpret_cast<const __nv_bfloat162*>((const __nv_bfloat16*)specu + base);
                float2 fa = __bfloat1622float2(sp[0]);
                float2 fb = __bfloat1622float2(sp[1]);
                o = make_float4(fa.x, fa.y, fb.x, fb.y);
            }
        } else {
            const float s = sc[j];
            o = make_float4(c_nf4[q[j].x & 15] * s, c_nf4[q[j].y & 15] * s,
                            c_nf4[q[j].z & 15] * s, c_nf4[q[j].w & 15] * s);
        }
        // Streaming store: output never re-read; keep L2 for quant-row dedup.
        __stcs(reinterpret_cast<float4*>(out + (size_t)(tok0 + j) * DIM + d), o);
    }
}

extern "C" void kernel_launch(void* const* d_in, const int* in_sizes, int n_in,
                              void* d_out, int out_size) {
    const void*  ids    = d_in[0];
    const int*   quant  = (const int*)d_in[1];
    const float* scales = (const float*)d_in[2];
    const unsigned short* spec = (const unsigned short*)d_in[3];
    const void*  sidx   = d_in[4];
    float* out = (float*)d_out;

    tok_embed_kernel<<<NTOK / TPB, 256>>>(ids, quant, scales, spec, sidx, out);
}

// round 11
// speedup vs baseline: 1.0918x; 1.0291x over previous
#include <cuda_runtime.h>
#include <cuda_fp16.h>
#include <cuda_bf16.h>
#include <cstdint>

// TokenAwareEmbedding: per-token NF4 dequant + special-token override.
// Single-launch kernel; all prologue work (width/dtype detection, special
// binary search) is warp-local, sync-free, and overlapped with the gather
// loads' latency.
//   0: input_ids          int32|int64 [8, 2048]
//   1: main_quantized     int32       [804112, 64]
//   2: main_scales        fp32        [804112]
//   3: special_embeddings fp32|fp16|bf16 [256, 1024]
//   4: special_indices    int32|int64 [256] (sorted)
// output: fp32 [8, 2048, 1024]

#define VOCAB 50257
#define DIM 1024
#define NTOK (8 * 2048)
#define NSPEC 256
#define TPB 8            // tokens per block

__constant__ float c_nf4[16] = {
    -1.0f, -0.6962f, -0.5251f, -0.3949f, -0.2844f, -0.1848f, -0.0911f, 0.0f,
    0.0796f, 0.1609f, 0.2461f, 0.3379f, 0.4407f, 0.5626f, 0.723f, 1.0f};

__device__ __forceinline__ float finite_abs(float v) {
    return isfinite(v) ? fabsf(v) : 1e30f;
}

__global__ __launch_bounds__(256)
void tok_embed_kernel(const void* __restrict__ ids,
                      const int* __restrict__ quant,
                      const float* __restrict__ scales,
                      const unsigned short* __restrict__ specu,
                      const void* __restrict__ sidx,
                      float* __restrict__ out) {
    const int tid  = threadIdx.x;
    const int lane = tid & 31;
    const int tok0 = blockIdx.x * TPB;

    // ── width detection: int64 ids have zero odd int32 words (L2 broadcast) ──
    const int* w32 = (const int*)ids;
    const int accw = w32[1] | w32[3] | w32[5] | w32[7] |
                     w32[9] | w32[11] | w32[13] | w32[15];
    const bool wide = (accw == 0);   // uniform across all threads

    // ── load this CTA's 8 token ids (broadcast, L2-hot) ──
    int tkn[TPB];
    #pragma unroll
    for (int j = 0; j < TPB; j++) {
        long long tl = wide ? ((const long long*)ids)[tok0 + j]
                            : (long long)((const int*)ids)[tok0 + j];
        if (tl < 0) tl = 0;
        if (tl >= VOCAB) tl = VOCAB - 1;
        tkn[j] = (int)tl;
    }

    const int d = tid * 4;  // 4 consecutive dims per thread

    // ── Phase 1: issue all bulk gather loads IMMEDIATELY (no control flow) ──
    int4 q[TPB];
    float sc[TPB];
    #pragma unroll
    for (int j = 0; j < TPB; j++) {
        q[j]  = *reinterpret_cast<const int4*>(quant + (size_t)tkn[j] * DIM + d);
        sc[j] = __ldg(scales + tkn[j] * (DIM / 64) + (d >> 6));
    }

    // ── Overlapped: lane l binary-searches token (l&7) in global sidx ──
    // upper_bound; last-wins for duplicate sorted indices (XLA scatter).
    const int myt = tkn[lane & 7];
    int lo = 0, hi = NSPEC;
    #pragma unroll
    for (int it = 0; it < 8; it++) {
        int mid = (lo + hi) >> 1;
        long long sv = wide ? ((const long long*)sidx)[mid]
                            : (long long)((const int*)sidx)[mid];
        if (sv <= myt) lo = mid + 1; else hi = mid;
    }
    int myr = -1;
    if (lo > 0) {
        long long sv = wide ? ((const long long*)sidx)[lo - 1]
                            : (long long)((const int*)sidx)[lo - 1];
        if (sv == myt) myr = lo - 1;
    }

    // ── Overlapped: warp-local dtype detection (128 samples, broadcast) ──
    // mean |x| of N(0,1) ~ 0.798. bf16-read-as-fp16 -> mean ~1.8 (reject);
    // fp32-read-as-fp16/bf16 -> NaN/huge max (reject).
    float vh = 0.f, vb = 0.f, mh = 0.f, mb = 0.f;
    #pragma unroll
    for (int k = 0; k < 4; k++) {
        int i = lane + k * 32;
        float h = finite_abs(__half2float(((const __half*)specu)[i]));
        float b = finite_abs(__bfloat162float(((const __nv_bfloat16*)specu)[i]));
        vh += h; mh = fmaxf(mh, h);
        vb += b; mb = fmaxf(mb, b);
    }
    #pragma unroll
    for (int o = 16; o > 0; o >>= 1) {
        vh += __shfl_xor_sync(0xFFFFFFFFu, vh, o);
        mh = fmaxf(mh, __shfl_xor_sync(0xFFFFFFFFu, mh, o));
        vb += __shfl_xor_sync(0xFFFFFFFFu, vb, o);
        mb = fmaxf(mb, __shfl_xor_sync(0xFFFFFFFFu, mb, o));
    }
    vh *= (1.0f / 128.0f);
    vb *= (1.0f / 128.0f);
    int dt;
    if (mh < 10.f && fabsf(vh - 0.8f) < 0.3f)      dt = 1;  // fp16
    else if (mb < 10.f && fabsf(vb - 0.8f) < 0.3f) dt = 2;  // bf16
    else                                            dt = 0;  // fp32

    // ── distribute search results within the warp ──
    int rrow[TPB];
    #pragma unroll
    for (int j = 0; j < TPB; j++)
        rrow[j] = __shfl_sync(0xFFFFFFFFu, myr, j);

    // ── Phase 2: compute + streaming stores (rare special branch only) ──
    #pragma unroll
    for (int j = 0; j < TPB; j++) {
        const int r = rrow[j];
        float4 o;
        if (r >= 0) {
            const size_t base = (size_t)r * DIM + d;
            if (dt == 0) {
                o = *reinterpret_cast<const float4*>((const float*)specu + base);
            } else if (dt == 1) {
                const __half2* sp = reinterpret_cast<const __half2*>((const __half*)specu + base);
                float2 fa = __half22float2(sp[0]);
                float2 fb = __half22float2(sp[1]);
                o = make_float4(fa.x, fa.y, fb.x, fb.y);
            } else {
                const __nv_bfloat162* sp =
                    reinterpret_cast<const __nv_bfloat162*>((const __nv_bfloat16*)specu + base);
                float2 fa = __bfloat1622float2(sp[0]);
                float2 fb = __bfloat1622float2(sp[1]);
                o = make_float4(fa.x, fa.y, fb.x, fb.y);
            }
        } else {
            const float s = sc[j];
            o = make_float4(c_nf4[q[j].x & 15] * s, c_nf4[q[j].y & 15] * s,
                            c_nf4[q[j].z & 15] * s, c_nf4[q[j].w & 15] * s);
        }
        // Streaming store: output never re-read; keep L2 for quant-row dedup.
        __stcs(reinterpret_cast<float4*>(out + (size_t)(tok0 + j) * DIM + d), o);
    }
}

extern "C" void kernel_launch(void* const* d_in, const int* in_sizes, int n_in,
                              void* d_out, int out_size) {
    const void*  ids    = d_in[0];
    const int*   quant  = (const int*)d_in[1];
    const float* scales = (const float*)d_in[2];
    const unsigned short* spec = (const unsigned short*)d_in[3];
    const void*  sidx   = d_in[4];
    float* out = (float*)d_out;

    tok_embed_kernel<<<NTOK / TPB, 256>>>(ids, quant, scales, spec, sidx, out);
}

// round 12
// speedup vs baseline: 1.1007x; 1.0081x over previous
#include <cuda_runtime.h>
#include <cuda_fp16.h>
#include <cuda_bf16.h>
#include <cstdint>

// TokenAwareEmbedding: persistent software-pipelined gather/dequant.
//   0: input_ids          int32|int64 [8, 2048]
//   1: main_quantized     int32       [804112, 64]
//   2: main_scales        fp32        [804112]
//   3: special_embeddings fp32|fp16|bf16 [256, 1024]
//   4: special_indices    int32|int64 [256] (sorted)
// output: fp32 [8, 2048, 1024]

#define VOCAB 50257
#define DIM 1024
#define NTOK (8 * 2048)
#define NSPEC 256
#define TPB 4                   // tokens per batch
#define NBATCH (NTOK / TPB)     // 4096
#define GRID 592                // ~4 CTAs/SM persistent

__constant__ float c_nf4[16] = {
    -1.0f, -0.6962f, -0.5251f, -0.3949f, -0.2844f, -0.1848f, -0.0911f, 0.0f,
    0.0796f, 0.1609f, 0.2461f, 0.3379f, 0.4407f, 0.5626f, 0.723f, 1.0f};

__device__ __forceinline__ float finite_abs(float v) {
    return isfinite(v) ? fabsf(v) : 1e30f;
}

__global__ __launch_bounds__(256)
void tok_embed_kernel(const void* __restrict__ ids,
                      const int* __restrict__ quant,
                      const float* __restrict__ scales,
                      const unsigned short* __restrict__ specu,
                      const void* __restrict__ sidx,
                      float* __restrict__ out) {
    __shared__ int s_sidx[NSPEC];
    const int tid  = threadIdx.x;
    const int lane = tid & 31;

    // ── CTA prologue (paid once per persistent CTA) ──
    // width: int64 ids have zero odd int32 words (L2 broadcast)
    const int* w32 = (const int*)ids;
    const int accw = w32[1] | w32[3] | w32[5] | w32[7] |
                     w32[9] | w32[11] | w32[13] | w32[15];
    const bool wide = (accw == 0);

    if (tid < NSPEC)
        s_sidx[tid] = wide ? (int)((const long long*)sidx)[tid]
                           : ((const int*)sidx)[tid];

    // dtype detect, warp-local (128 samples). mean|x| of N(0,1) ~ 0.798;
    // bf16-as-fp16 -> ~1.8 (reject); fp32-as-16bit -> NaN/huge (reject).
    float vh = 0.f, vb = 0.f, mh = 0.f, mb = 0.f;
    #pragma unroll
    for (int k = 0; k < 4; k++) {
        int i = lane + k * 32;
        float h = finite_abs(__half2float(((const __half*)specu)[i]));
        float b = finite_abs(__bfloat162float(((const __nv_bfloat16*)specu)[i]));
        vh += h; mh = fmaxf(mh, h);
        vb += b; mb = fmaxf(mb, b);
    }
    #pragma unroll
    for (int o = 16; o > 0; o >>= 1) {
        vh += __shfl_xor_sync(0xFFFFFFFFu, vh, o);
        mh = fmaxf(mh, __shfl_xor_sync(0xFFFFFFFFu, mh, o));
        vb += __shfl_xor_sync(0xFFFFFFFFu, vb, o);
        mb = fmaxf(mb, __shfl_xor_sync(0xFFFFFFFFu, mb, o));
    }
    vh *= (1.0f / 128.0f);
    vb *= (1.0f / 128.0f);
    int dt;
    if (mh < 10.f && fabsf(vh - 0.8f) < 0.3f)      dt = 1;  // fp16
    else if (mb < 10.f && fabsf(vb - 0.8f) < 0.3f) dt = 2;  // bf16
    else                                            dt = 0;  // fp32
    __syncthreads();

    const int d = tid * 4;  // 4 consecutive dims per thread

    // fetch: read ids, ISSUE gather loads first, then overlapped SMEM search
    auto fetch = [&](int bi, int* tkn, int4* q, float* sc, int* rr) {
        const int tok0 = bi * TPB;
        #pragma unroll
        for (int j = 0; j < TPB; j++) {
            long long tl = wide ? ((const long long*)ids)[tok0 + j]
                                : (long long)((const int*)ids)[tok0 + j];
            if (tl < 0) tl = 0;
            if (tl >= VOCAB) tl = VOCAB - 1;
            tkn[j] = (int)tl;
        }
        #pragma unroll
        for (int j = 0; j < TPB; j++) {
            q[j]  = *reinterpret_cast<const int4*>(quant + (size_t)tkn[j] * DIM + d);
            sc[j] = __ldg(scales + tkn[j] * (DIM / 64) + (d >> 6));
        }
        // lane (l&3) searches its token in SMEM sidx; upper_bound, last-wins
        const int myt = tkn[lane & 3];
        int lo = 0, hi = NSPEC;
        #pragma unroll
        for (int it = 0; it < 8; it++) {
            int mid = (lo + hi) >> 1;
            if (s_sidx[mid] <= myt) lo = mid + 1; else hi = mid;
        }
        const int myr = (lo > 0 && s_sidx[lo - 1] == myt) ? (lo - 1) : -1;
        #pragma unroll
        for (int j = 0; j < TPB; j++)
            rr[j] = __shfl_sync(0xFFFFFFFFu, myr, j);
    };

    // emit: dequant (or rare special override) + streaming stores
    auto emit = [&](int bi, const int4* q, const float* sc, const int* rr) {
        const int tok0 = bi * TPB;
        #pragma unroll
        for (int j = 0; j < TPB; j++) {
            const int r = rr[j];
            float4 o;
            if (r >= 0) {
                const size_t base = (size_t)r * DIM + d;
                if (dt == 0) {
                    o = *reinterpret_cast<const float4*>((const float*)specu + base);
                } else if (dt == 1) {
                    const __half2* sp = reinterpret_cast<const __half2*>((const __half*)specu + base);
                    float2 fa = __half22float2(sp[0]);
                    float2 fb = __half22float2(sp[1]);
                    o = make_float4(fa.x, fa.y, fb.x, fb.y);
                } else {
                    const __nv_bfloat162* sp =
                        reinterpret_cast<const __nv_bfloat162*>((const __nv_bfloat16*)specu + base);
                    float2 fa = __bfloat1622float2(sp[0]);
                    float2 fb = __bfloat1622float2(sp[1]);
                    o = make_float4(fa.x, fa.y, fb.x, fb.y);
                }
            } else {
                const float s = sc[j];
                o = make_float4(c_nf4[q[j].x & 15] * s, c_nf4[q[j].y & 15] * s,
                                c_nf4[q[j].z & 15] * s, c_nf4[q[j].w & 15] * s);
            }
            __stcs(reinterpret_cast<float4*>(out + (size_t)(tok0 + j) * DIM + d), o);
        }
    };

    // ── persistent grid-stride loop, register double-buffered ──
    int bi = blockIdx.x;
    if (bi >= NBATCH) return;
    int tknA[TPB], rrA[TPB];
    int4 qA[TPB];
    float scA[TPB];
    fetch(bi, tknA, qA, scA, rrA);

    for (;;) {
        const int bn = bi + GRID;
        if (bn < NBATCH) {
            int tknB[TPB], rrB[TPB];
            int4 qB[TPB];
            float scB[TPB];
            fetch(bn, tknB, qB, scB, rrB);   // next batch's loads in flight...
            emit(bi, qA, scA, rrA);          // ...while this batch computes/stores
            #pragma unroll
            for (int j = 0; j < TPB; j++) {
                tknA[j] = tknB[j]; rrA[j] = rrB[j];
                qA[j] = qB[j]; scA[j] = scB[j];
            }
            bi = bn;
        } else {
            emit(bi, qA, scA, rrA);
            break;
        }
    }
}

extern "C" void kernel_launch(void* const* d_in, const int* in_sizes, int n_in,
                              void* d_out, int out_size) {
    const void*  ids    = d_in[0];
    const int*   quant  = (const int*)d_in[1];
    const float* scales = (const float*)d_in[2];
    const unsigned short* spec = (const unsigned short*)d_in[3];
    const void*  sidx   = d_in[4];
    float* out = (float*)d_out;

    tok_embed_kernel<<<GRID, 256>>>(ids, quant, scales, spec, sidx, out);
}